// round 16
// baseline (speedup 1.0000x reference)
#include <cuda_runtime.h>
#include <cuda_bf16.h>
#include <cstdint>

// Problem constants
#define CH 512
#define TT 4096
#define BB 2
#define KS 12
#define NN 10
#define QS 8           // partials: one per 64-row m-block (h4 reduced in-CTA)

// ---------------------------------------------------------------------------
// Scratch (device globals; allocation is forbidden)
// ---------------------------------------------------------------------------
__device__ float  g_band_p[QS * BB * KS * TT];   // 3.1 MB
__device__ float  g_rows_p[QS * BB * NN * TT];   // 2.6 MB
__device__ float2 g_ls2[NN * TT];                // ls[r][t] = {b0, b1}
__device__ double g_total;
__device__ int    g_done;

// ---------------------------------------------------------------------------
// PTX helpers (baseline sm_80+: ldmatrix + mma.sync only)
// ---------------------------------------------------------------------------
__device__ __forceinline__ uint32_t smem_u32(const void* p) {
    uint32_t a;
    asm("{ .reg .u64 t; cvta.to.shared.u64 t, %1; cvt.u32.u64 %0, t; }"
        : "=r"(a) : "l"(p));
    return a;
}
__device__ __forceinline__ void ldsm_x4(uint32_t* r, uint32_t addr) {
    asm volatile("ldmatrix.sync.aligned.m8n8.x4.shared.b16 {%0,%1,%2,%3}, [%4];"
                 : "=r"(r[0]), "=r"(r[1]), "=r"(r[2]), "=r"(r[3]) : "r"(addr));
}
__device__ __forceinline__ void ldsm_x4_t(uint32_t* r, uint32_t addr) {
    asm volatile("ldmatrix.sync.aligned.m8n8.x4.trans.shared.b16 {%0,%1,%2,%3}, [%4];"
                 : "=r"(r[0]), "=r"(r[1]), "=r"(r[2]), "=r"(r[3]) : "r"(addr));
}
__device__ __forceinline__ void mma16816(float* d, const uint32_t* a,
                                         const uint32_t* b) {
    asm volatile(
        "mma.sync.aligned.m16n8k16.row.col.f32.bf16.bf16.f32 "
        "{%0,%1,%2,%3}, {%4,%5,%6,%7}, {%8,%9}, {%0,%1,%2,%3};"
        : "+f"(d[0]), "+f"(d[1]), "+f"(d[2]), "+f"(d[3])
        : "r"(a[0]), "r"(a[1]), "r"(a[2]), "r"(a[3]), "r"(b[0]), "r"(b[1]));
}

__device__ __forceinline__ float logsigf(float x) {
    float e = __expf(-fabsf(x));
    return fminf(x, 0.f) - __logf(1.f + e);
}

// ---------------------------------------------------------------------------
// Kernel A: FUSED  GEMM (mma.sync bf16) + band/rows partials.
//   BM=64 x BN=128 tiles, 256 threads, 3 CTAs/SM (occupancy play).
// ---------------------------------------------------------------------------
#define BM 64
#define BN 128
#define BKT 32
#define APAD 40
#define BPAD 136
#define CPAD 136
#define FEW 144
#define NKT (CH / BKT)       // 16

#define AS_OFF 0
#define BS_OFF 5120          // A = 64*40*2 = 5120
#define C_OFF  0             // Cs = 64*136*2 = 17408
#define FE_OFF 17408         // FEs = 16*72*4 = 4608
#define FER_OFF 22016        // FERs = 512
#define SMEM_BYTES 24576     // RED band phase: 4*12*64*8 = 24576

__global__ __launch_bounds__(256, 3) void fused_k(const float* __restrict__ fc,
                                                  const float* __restrict__ fe,
                                                  const float* __restrict__ W,
                                                  const float* __restrict__ bias) {
    __shared__ __align__(16) char smbuf[SMEM_BYTES];
    __nv_bfloat16* As = (__nv_bfloat16*)(smbuf + AS_OFF);
    __nv_bfloat16* Bs = (__nv_bfloat16*)(smbuf + BS_OFF);

    const int tid  = threadIdx.x;
    const int lane = tid & 31;
    const int wid  = tid >> 5;
    const int wm   = wid >> 2;          // 0..1 (32-row halves)
    const int wn   = wid & 3;           // 0..3 (32-col groups)

    const int b  = blockIdx.z;
    const int t0 = blockIdx.x * BN;
    const int d0 = blockIdx.y * BM;

    if (blockIdx.x == 0 && blockIdx.y == 0 && blockIdx.z == 0 && tid == 0) {
        g_total = 0.0;
        g_done  = 0;
    }

    const uint32_t as_base = smem_u32(As);
    const uint32_t bs_base = smem_u32(Bs);

    const int grp = lane >> 3, lr = lane & 7;
    const uint32_t a_lane = (uint32_t)((wm * 32 + lr + (grp & 1) * 8) * APAD * 2
                                       + ((grp >> 1) * 8) * 2);
    const uint32_t b_lane = (uint32_t)(((grp & 1) * 8 + lr) * BPAD * 2
                                       + (wn * 32 + (grp >> 1) * 8) * 2);

    float acc[2][4][4];
#pragma unroll
    for (int i = 0; i < 2; i++)
#pragma unroll
        for (int j = 0; j < 4; j++)
#pragma unroll
            for (int q = 0; q < 4; q++) acc[i][j][q] = 0.f;

    const float* fcb = fc + (size_t)b * CH * TT;

    float4 wreg[2];   // A: 64 rows x 8 float4 = 512 over 256 threads
    float4 breg[4];   // B: 32 rows x 32 float4 = 1024 over 256 threads

    // ---- prefetch tile 0
#pragma unroll
    for (int j = 0; j < 2; j++) {
        int seg = tid + j * 256;                  // 0..511
        int row = seg >> 3, c4 = seg & 7;
        wreg[j] = *(const float4*)(W + (size_t)(d0 + row) * CH + c4 * 4);
    }
#pragma unroll
    for (int j = 0; j < 4; j++) {
        int seg = tid + j * 256;
        int row = seg >> 5, c4 = seg & 31;
        breg[j] = *(const float4*)(fcb + (size_t)row * TT + t0 + c4 * 4);
    }

    for (int kt = 0; kt < NKT; kt++) {
        __syncthreads();
#pragma unroll
        for (int j = 0; j < 2; j++) {
            int seg = tid + j * 256;
            int row = seg >> 3, c4 = seg & 7;
            float4 v = wreg[j];
            __nv_bfloat162* p = (__nv_bfloat162*)(As + row * APAD + c4 * 4);
            p[0] = __floats2bfloat162_rn(v.x, v.y);
            p[1] = __floats2bfloat162_rn(v.z, v.w);
        }
#pragma unroll
        for (int j = 0; j < 4; j++) {
            int seg = tid + j * 256;
            int row = seg >> 5, c4 = seg & 31;
            float4 v = breg[j];
            __nv_bfloat162* p = (__nv_bfloat162*)(Bs + row * BPAD + c4 * 4);
            p[0] = __floats2bfloat162_rn(v.x, v.y);
            p[1] = __floats2bfloat162_rn(v.z, v.w);
        }
        __syncthreads();

        if (kt + 1 < NKT) {
            const int k0 = (kt + 1) * BKT;
#pragma unroll
            for (int j = 0; j < 2; j++) {
                int seg = tid + j * 256;
                int row = seg >> 3, c4 = seg & 7;
                wreg[j] = *(const float4*)(W + (size_t)(d0 + row) * CH + k0 + c4 * 4);
            }
#pragma unroll
            for (int j = 0; j < 4; j++) {
                int seg = tid + j * 256;
                int row = seg >> 5, c4 = seg & 31;
                breg[j] = *(const float4*)(fcb + (size_t)(k0 + row) * TT + t0 + c4 * 4);
            }
        }

#pragma unroll
        for (int ks = 0; ks < 2; ks++) {
            uint32_t af[2][4];
#pragma unroll
            for (int fm = 0; fm < 2; fm++)
                ldsm_x4(af[fm], as_base + a_lane
                                + (uint32_t)(fm * 16 * APAD * 2 + ks * 16 * 2));
            uint32_t bf[2][4];
#pragma unroll
            for (int fn = 0; fn < 2; fn++)
                ldsm_x4_t(bf[fn], bs_base + b_lane
                                  + (uint32_t)(ks * 16 * BPAD * 2 + fn * 16 * 2));
#pragma unroll
            for (int fm = 0; fm < 2; fm++)
#pragma unroll
                for (int nf = 0; nf < 4; nf++)
                    mma16816(acc[fm][nf], af[fm], &bf[nf >> 1][(nf & 1) * 2]);
        }
    }

    // ================= epilogue 1: acc + bias -> c tile in SMEM (bf16) =====
    __syncthreads();
    __nv_bfloat16* Cs = (__nv_bfloat16*)(smbuf + C_OFF);
    {
        const int rbase = lane >> 2;
        const int cbase = (lane & 3) * 2;
#pragma unroll
        for (int fm = 0; fm < 2; fm++) {
            const int dd = wm * 32 + fm * 16 + rbase;       // local channel
            const float bi_lo = bias[d0 + dd];
            const float bi_hi = bias[d0 + dd + 8];
#pragma unroll
            for (int nf = 0; nf < 4; nf++) {
                const int tt = wn * 32 + nf * 8 + cbase;
                *(__nv_bfloat162*)(Cs + dd * CPAD + tt) =
                    __floats2bfloat162_rn(acc[fm][nf][0] + bi_lo,
                                          acc[fm][nf][1] + bi_lo);
                *(__nv_bfloat162*)(Cs + (dd + 8) * CPAD + tt) =
                    __floats2bfloat162_rn(acc[fm][nf][2] + bi_hi,
                                          acc[fm][nf][3] + bi_hi);
            }
        }
    }
    __syncthreads();

    // ================= epilogue 2: band + rows partials ====================
    __nv_bfloat162* FEs  = (__nv_bfloat162*)(smbuf + FE_OFF);   // [16][72]
    __nv_bfloat162* FERs = (__nv_bfloat162*)(smbuf + FER_OFF);  // [16][8]
    const int t2 = (tid & 63) * 2;
    const int h4 = tid >> 6;
    const float* feb = fe + (size_t)b * CH * TT;

    float accB[KS][2];
    float accR[NN][2];
#pragma unroll
    for (int k = 0; k < KS; k++) accB[k][0] = accB[k][1] = 0.f;
#pragma unroll
    for (int r = 0; r < NN; r++) accR[r][0] = accR[r][1] = 0.f;

    for (int cc = 0; cc < BM / 16; cc++) {      // 4 chunks of 16 channels
        const int chbase = d0 + cc * 16;
        for (int i = tid; i < 16 * (FEW / 2); i += 256) {
            int ch = i / (FEW / 2), jj = (i % (FEW / 2)) * 2;
            int col = t0 + jj;
            const float* row = feb + (size_t)(chbase + ch) * TT;
            if (col < TT) {
                float2 x = *(const float2*)(row + col);
                FEs[ch * (FEW / 2) + jj / 2] = __floats2bfloat162_rn(x.x, x.y);
            } else {
                FEs[ch * (FEW / 2) + jj / 2] = __floats2bfloat162_rn(0.f, 0.f);
            }
        }
        for (int i = tid; i < 16 * 16; i += 256) {
            int ch = i >> 4, r = i & 15;
            float v = (r < NN) ? feb[(size_t)(chbase + ch) * TT + r] : 0.f;
            ((__nv_bfloat16*)FERs)[ch * 16 + r] = __float2bfloat16(v);
        }
        __syncthreads();

#pragma unroll
        for (int j = 0; j < 4; j++) {
            const int lch = h4 * 4 + j;          // channel in chunk (0..15)
            const int ch  = cc * 16 + lch;       // block-local channel, for Cs
            __nv_bfloat162 cv = *(__nv_bfloat162*)(Cs + ch * CPAD + t2);
            float c0 = __bfloat162float(cv.x);
            float c1 = __bfloat162float(cv.y);

            float w[14];
#pragma unroll
            for (int p = 0; p < 7; p++) {
                __nv_bfloat162 v = FEs[lch * (FEW / 2) + t2 / 2 + p];
                w[2 * p]     = __bfloat162float(v.x);
                w[2 * p + 1] = __bfloat162float(v.y);
            }
#pragma unroll
            for (int k = 0; k < KS; k++) {
                accB[k][0] += w[k] * c0;
                accB[k][1] += w[k + 1] * c1;
            }
#pragma unroll
            for (int p = 0; p < 5; p++) {
                __nv_bfloat162 v = FERs[lch * 8 + p];
                float f0 = __bfloat162float(v.x);
                float f1 = __bfloat162float(v.y);
                accR[2 * p][0]     += f0 * c0;
                accR[2 * p][1]     += f0 * c1;
                accR[2 * p + 1][0] += f1 * c0;
                accR[2 * p + 1][1] += f1 * c1;
            }
        }
        __syncthreads();
    }

    // ================= epilogue 3: reduce h4 quarters in SMEM, write QS=8 ==
    float2* RED = (float2*)smbuf;                  // overlays Cs/FEs (dead)
    const int q  = blockIdx.y;                     // 0..7 (m-block)
    const int c2i = t2 >> 1;                       // 0..63

    // Phase A: band  — RED[h4][KS][64]  (24.6 KB)
#pragma unroll
    for (int k = 0; k < KS; k++)
        RED[(h4 * KS + k) * 64 + c2i] = make_float2(accB[k][0], accB[k][1]);
    __syncthreads();
    for (int e = tid; e < KS * 64; e += 256) {
        int k = e >> 6, c2 = e & 63;
        float2 s0 = RED[(0 * KS + k) * 64 + c2];
        float2 s1 = RED[(1 * KS + k) * 64 + c2];
        float2 s2 = RED[(2 * KS + k) * 64 + c2];
        float2 s3 = RED[(3 * KS + k) * 64 + c2];
        float2 s = make_float2((s0.x + s1.x) + (s2.x + s3.x),
                               (s0.y + s1.y) + (s2.y + s3.y));
        *(float2*)&g_band_p[(((size_t)q * BB + b) * KS + k) * TT + t0 + c2 * 2] = s;
    }
    __syncthreads();

    // Phase B: rows  — RED[h4][NN][64]  (20.5 KB)
#pragma unroll
    for (int r = 0; r < NN; r++)
        RED[(h4 * NN + r) * 64 + c2i] = make_float2(accR[r][0], accR[r][1]);
    __syncthreads();
    for (int e = tid; e < NN * 64; e += 256) {
        int r = e >> 6, c2 = e & 63;
        float2 s0 = RED[(0 * NN + r) * 64 + c2];
        float2 s1 = RED[(1 * NN + r) * 64 + c2];
        float2 s2 = RED[(2 * NN + r) * 64 + c2];
        float2 s3 = RED[(3 * NN + r) * 64 + c2];
        float2 s = make_float2((s0.x + s1.x) + (s2.x + s3.x),
                               (s0.y + s1.y) + (s2.y + s3.y));
        *(float2*)&g_rows_p[(((size_t)q * BB + b) * NN + r) * TT + t0 + c2 * 2] = s;
    }
}

// ---------------------------------------------------------------------------
// Kernel B: combine partials (QS=8) + positives loss + interleaved ls table
// ---------------------------------------------------------------------------
__global__ __launch_bounds__(256) void combine_k() {
    const int NB = BB * KS * TT;
    const int NR = BB * NN * TT;
    int i = blockIdx.x * blockDim.x + threadIdx.x;
    double local = 0.0;
    if (i < NB) {
        float v = 0.f;
#pragma unroll
        for (int q = 0; q < QS; q++) v += g_band_p[(size_t)q * NB + i];
        int s = i % TT;
        int k = (i / TT) % KS;
        if (s + k < TT) local = (double)logsigf(v);
    } else if (i < NB + NR) {
        int j = i - NB;
        float v = 0.f;
#pragma unroll
        for (int q = 0; q < QS; q++) v += g_rows_p[(size_t)q * NR + j];
        int bq = j / (NN * TT);
        int r  = (j / TT) % NN;
        int s  = j % TT;
        float* dst = (float*)&g_ls2[(size_t)r * TT + s];
        dst[bq] = logsigf(-v);
    }
#pragma unroll
    for (int off = 16; off; off >>= 1)
        local += __shfl_down_sync(0xffffffffu, local, off);
    __shared__ double warp_sums[8];
    int lane = threadIdx.x & 31, wid = threadIdx.x >> 5;
    if (lane == 0) warp_sums[wid] = local;
    __syncthreads();
    if (wid == 0) {
        local = (lane < 8) ? warp_sums[lane] : 0.0;
#pragma unroll
        for (int off = 4; off; off >>= 1)
            local += __shfl_down_sync(0xffffffffu, local, off);
        if (lane == 0 && local != 0.0) atomicAdd(&g_total, local);
    }
}

// ---------------------------------------------------------------------------
// Kernel C: negatives — float2 gathers (Round-10 measured best) + final write
// ---------------------------------------------------------------------------
#define LGRID 960

__global__ __launch_bounds__(256) void loss_k(const int* __restrict__ neg_idx,
                                              float* __restrict__ out) {
    const int gid    = blockIdx.x * 256 + threadIdx.x;
    const int stride = LGRID * 256;            // 245760
    const int i0 = gid;
    const int i1 = gid + stride;
    const int r0 = i0 % NN, s0 = (i0 / NN) % TT, k0 = i0 / (NN * TT);
    const int r1 = i1 % NN, s1 = (i1 / NN) % TT, k1 = i1 / (NN * TT);
    int idx0 = __ldg(&neg_idx[(k0 * TT + s0) * NN + r0]);
    int idx1 = __ldg(&neg_idx[(k1 * TT + s1) * NN + r1]);
    float2 v0 = g_ls2[(size_t)r0 * TT + idx0];
    float2 v1 = g_ls2[(size_t)r1 * TT + idx1];
    float fsum = (v0.x + v0.y) + (v1.x + v1.y);
    double local = (double)NN * (double)fsum;

#pragma unroll
    for (int off = 16; off; off >>= 1)
        local += __shfl_down_sync(0xffffffffu, local, off);
    __shared__ double warp_sums[8];
    int lane = threadIdx.x & 31, wid = threadIdx.x >> 5;
    if (lane == 0) warp_sums[wid] = local;
    __syncthreads();
    if (wid == 0 && lane == 0) {
        local = 0.0;
#pragma unroll
        for (int w = 0; w < 8; w++) local += warp_sums[w];
        atomicAdd(&g_total, local);
        __threadfence();
        int done = atomicAdd(&g_done, 1);
        if (done == LGRID - 1) {
            __threadfence();
            double tot = atomicAdd(&g_total, 0.0);
            out[0] = (float)tot;
        }
    }
}

// ---------------------------------------------------------------------------
// Launch
// ---------------------------------------------------------------------------
extern "C" void kernel_launch(void* const* d_in, const int* in_sizes, int n_in,
                              void* d_out, int out_size) {
    const float* fe   = (const float*)d_in[0];  // feat_enc     [B,C,T]
    const float* fc   = (const float*)d_in[1];  // feat_context [B,C,T]
    const float* W    = (const float*)d_in[2];  // [C,C]
    const float* bias = (const float*)d_in[3];  // [C]
    const int*   neg  = (const int*)d_in[4];    // [K_STEPS,T,NUM_NEG]

    fused_k<<<dim3(TT / BN, CH / BM, BB), 256>>>(fc, fe, W, bias);

    const int NTOT = BB * (KS + NN) * TT;
    combine_k<<<(NTOT + 255) / 256, 256>>>();

    loss_k<<<LGRID, 256>>>(neg, (float*)d_out);
}

// round 17
// speedup vs baseline: 1.2573x; 1.2573x over previous
#include <cuda_runtime.h>
#include <cuda_bf16.h>
#include <cstdint>

// Problem constants
#define CH 512
#define TT 4096
#define BB 2
#define KS 12
#define NN 10
#define QS 4           // partials: one per m-block (h4 reduced in-CTA)

// ---------------------------------------------------------------------------
// Scratch (device globals; allocation is forbidden)
// ---------------------------------------------------------------------------
__device__ __nv_bfloat16 g_Wb[CH * CH];          // W in bf16, row-major [d][e]
__device__ float  g_band_p[QS * BB * KS * TT];   // 1.6 MB
__device__ float  g_rows_p[QS * BB * NN * TT];   // 1.3 MB
__device__ float2 g_ls2[NN * TT];                // ls[r][t] = {b0, b1}
__device__ double g_total;
__device__ int    g_done;

// ---------------------------------------------------------------------------
// PTX helpers (baseline sm_80+: ldmatrix + mma.sync only)
// ---------------------------------------------------------------------------
__device__ __forceinline__ uint32_t smem_u32(const void* p) {
    uint32_t a;
    asm("{ .reg .u64 t; cvta.to.shared.u64 t, %1; cvt.u32.u64 %0, t; }"
        : "=r"(a) : "l"(p));
    return a;
}
__device__ __forceinline__ void ldsm_x4(uint32_t* r, uint32_t addr) {
    asm volatile("ldmatrix.sync.aligned.m8n8.x4.shared.b16 {%0,%1,%2,%3}, [%4];"
                 : "=r"(r[0]), "=r"(r[1]), "=r"(r[2]), "=r"(r[3]) : "r"(addr));
}
__device__ __forceinline__ void ldsm_x4_t(uint32_t* r, uint32_t addr) {
    asm volatile("ldmatrix.sync.aligned.m8n8.x4.trans.shared.b16 {%0,%1,%2,%3}, [%4];"
                 : "=r"(r[0]), "=r"(r[1]), "=r"(r[2]), "=r"(r[3]) : "r"(addr));
}
__device__ __forceinline__ void mma16816(float* d, const uint32_t* a,
                                         const uint32_t* b) {
    asm volatile(
        "mma.sync.aligned.m16n8k16.row.col.f32.bf16.bf16.f32 "
        "{%0,%1,%2,%3}, {%4,%5,%6,%7}, {%8,%9}, {%0,%1,%2,%3};"
        : "+f"(d[0]), "+f"(d[1]), "+f"(d[2]), "+f"(d[3])
        : "r"(a[0]), "r"(a[1]), "r"(a[2]), "r"(a[3]), "r"(b[0]), "r"(b[1]));
}

__device__ __forceinline__ float logsigf(float x) {
    float e = __expf(-fabsf(x));
    return fminf(x, 0.f) - __logf(1.f + e);
}

// ---------------------------------------------------------------------------
// Kernel A: convert W to bf16, zero total + completion counter
// ---------------------------------------------------------------------------
__global__ void convw_k(const float* __restrict__ W) {
    int i = blockIdx.x * blockDim.x + threadIdx.x;   // over float2
    if (i == 0) { g_total = 0.0; g_done = 0; }
    if (i < CH * CH / 2) {
        float2 v = ((const float2*)W)[i];
        ((__nv_bfloat162*)g_Wb)[i] = __floats2bfloat162_rn(v.x, v.y);
    }
}

// ---------------------------------------------------------------------------
// Kernel B: FUSED  GEMM (mma.sync bf16) + band/rows partials.
//   Mainloop: Round-10 measured-best (single-buffer, BM=128, BN=128).
//   Epilogue 2: 4 chunks of 32 channels (halved barriers/staging overhead).
// ---------------------------------------------------------------------------
#define BM 128
#define BN 128
#define BKT 32
#define APAD 40
#define BPAD 136
#define CPAD 136
#define FEW 144
#define CCH 32               // channels per epilogue-2 chunk

#define AS_OFF 0
#define BS_OFF 10240
#define C_OFF  0
#define FE_OFF 34816         // FEs = 32*72*4 = 9216
#define FER_OFF 44032        // FERs = 32*16*2 = 1024
#define SMEM_BYTES 45056

__global__ __launch_bounds__(256, 2) void fused_k(const float* __restrict__ fc,
                                                  const float* __restrict__ fe,
                                                  const float* __restrict__ bias) {
    __shared__ __align__(16) char smbuf[SMEM_BYTES];
    __nv_bfloat16* As = (__nv_bfloat16*)(smbuf + AS_OFF);
    __nv_bfloat16* Bs = (__nv_bfloat16*)(smbuf + BS_OFF);

    const int tid  = threadIdx.x;
    const int lane = tid & 31;
    const int wid  = tid >> 5;
    const int wm   = wid >> 2;          // 0..1
    const int wn   = wid & 3;           // 0..3

    const int b  = blockIdx.z;
    const int t0 = blockIdx.x * BN;
    const int d0 = blockIdx.y * BM;

    const uint32_t as_base = smem_u32(As);
    const uint32_t bs_base = smem_u32(Bs);

    const int grp = lane >> 3, lr = lane & 7;
    const uint32_t a_lane = (uint32_t)((wm * 64 + lr + (grp & 1) * 8) * APAD * 2
                                       + ((grp >> 1) * 8) * 2);
    const uint32_t b_lane = (uint32_t)(((grp & 1) * 8 + lr) * BPAD * 2
                                       + (wn * 32 + (grp >> 1) * 8) * 2);

    float acc[4][4][4];
#pragma unroll
    for (int i = 0; i < 4; i++)
#pragma unroll
        for (int j = 0; j < 4; j++)
#pragma unroll
            for (int q = 0; q < 4; q++) acc[i][j][q] = 0.f;

    const float* fcb = fc + (size_t)b * CH * TT;

    uint4  areg[2];
    float4 breg[4];

    // ---- prefetch tile 0
#pragma unroll
    for (int j = 0; j < 2; j++) {
        int seg = tid + j * 256;
        int row = seg >> 2, c8 = seg & 3;
        areg[j] = *(const uint4*)(g_Wb + (size_t)(d0 + row) * CH + c8 * 8);
    }
#pragma unroll
    for (int j = 0; j < 4; j++) {
        int seg = tid + j * 256;
        int row = seg >> 5, c4 = seg & 31;
        breg[j] = *(const float4*)(fcb + (size_t)row * TT + t0 + c4 * 4);
    }

    for (int kt = 0; kt < CH / BKT; kt++) {
        __syncthreads();
#pragma unroll
        for (int j = 0; j < 2; j++) {
            int seg = tid + j * 256;
            int row = seg >> 2, c8 = seg & 3;
            *(uint4*)(As + row * APAD + c8 * 8) = areg[j];
        }
#pragma unroll
        for (int j = 0; j < 4; j++) {
            int seg = tid + j * 256;
            int row = seg >> 5, c4 = seg & 31;
            float4 v = breg[j];
            __nv_bfloat162* p = (__nv_bfloat162*)(Bs + row * BPAD + c4 * 4);
            p[0] = __floats2bfloat162_rn(v.x, v.y);
            p[1] = __floats2bfloat162_rn(v.z, v.w);
        }
        __syncthreads();

        if (kt + 1 < CH / BKT) {
            const int k0 = (kt + 1) * BKT;
#pragma unroll
            for (int j = 0; j < 2; j++) {
                int seg = tid + j * 256;
                int row = seg >> 2, c8 = seg & 3;
                areg[j] = *(const uint4*)(g_Wb + (size_t)(d0 + row) * CH + k0 + c8 * 8);
            }
#pragma unroll
            for (int j = 0; j < 4; j++) {
                int seg = tid + j * 256;
                int row = seg >> 5, c4 = seg & 31;
                breg[j] = *(const float4*)(fcb + (size_t)(k0 + row) * TT + t0 + c4 * 4);
            }
        }

#pragma unroll
        for (int ks = 0; ks < 2; ks++) {
            uint32_t af[4][4];
#pragma unroll
            for (int fm = 0; fm < 4; fm++)
                ldsm_x4(af[fm], as_base + a_lane
                                + (uint32_t)(fm * 16 * APAD * 2 + ks * 16 * 2));
            uint32_t bf[2][4];
#pragma unroll
            for (int fn = 0; fn < 2; fn++)
                ldsm_x4_t(bf[fn], bs_base + b_lane
                                  + (uint32_t)(ks * 16 * BPAD * 2 + fn * 16 * 2));
#pragma unroll
            for (int fm = 0; fm < 4; fm++)
#pragma unroll
                for (int nf = 0; nf < 4; nf++)
                    mma16816(acc[fm][nf], af[fm], &bf[nf >> 1][(nf & 1) * 2]);
        }
    }

    // ================= epilogue 1: acc + bias -> c tile in SMEM (bf16) =====
    __syncthreads();      // done reading As/Bs; Cs overlaps them
    __nv_bfloat16* Cs = (__nv_bfloat16*)(smbuf + C_OFF);
    {
        const int rbase = lane >> 2;
        const int cbase = (lane & 3) * 2;
#pragma unroll
        for (int fm = 0; fm < 4; fm++) {
            const int dd = wm * 64 + fm * 16 + rbase;       // local channel
            const float bi_lo = bias[d0 + dd];
            const float bi_hi = bias[d0 + dd + 8];
#pragma unroll
            for (int nf = 0; nf < 4; nf++) {
                const int tt = wn * 32 + nf * 8 + cbase;
                *(__nv_bfloat162*)(Cs + dd * CPAD + tt) =
                    __floats2bfloat162_rn(acc[fm][nf][0] + bi_lo,
                                          acc[fm][nf][1] + bi_lo);
                *(__nv_bfloat162*)(Cs + (dd + 8) * CPAD + tt) =
                    __floats2bfloat162_rn(acc[fm][nf][2] + bi_hi,
                                          acc[fm][nf][3] + bi_hi);
            }
        }
    }
    __syncthreads();

    // ================= epilogue 2: band + rows partials (32-ch chunks) =====
    __nv_bfloat162* FEs  = (__nv_bfloat162*)(smbuf + FE_OFF);   // [32][FEW/2]
    __nv_bfloat162* FERs = (__nv_bfloat162*)(smbuf + FER_OFF);  // [32][8]
    const int t2 = (tid & 63) * 2;
    const int h4 = tid >> 6;
    const float* feb = fe + (size_t)b * CH * TT;

    float accB[KS][2];
    float accR[NN][2];
#pragma unroll
    for (int k = 0; k < KS; k++) accB[k][0] = accB[k][1] = 0.f;
#pragma unroll
    for (int r = 0; r < NN; r++) accR[r][0] = accR[r][1] = 0.f;

    for (int cc = 0; cc < BM / CCH; cc++) {     // 4 chunks of 32 channels
        const int chbase = d0 + cc * CCH;
        for (int i = tid; i < CCH * (FEW / 2); i += 256) {   // 9 iterations
            int ch = i / (FEW / 2), jj = (i % (FEW / 2)) * 2;
            int col = t0 + jj;
            const float* row = feb + (size_t)(chbase + ch) * TT;
            if (col < TT) {
                float2 x = *(const float2*)(row + col);
                FEs[ch * (FEW / 2) + jj / 2] = __floats2bfloat162_rn(x.x, x.y);
            } else {
                FEs[ch * (FEW / 2) + jj / 2] = __floats2bfloat162_rn(0.f, 0.f);
            }
        }
        for (int i = tid; i < CCH * 16; i += 256) {          // 2 iterations
            int ch = i >> 4, r = i & 15;
            float v = (r < NN) ? feb[(size_t)(chbase + ch) * TT + r] : 0.f;
            ((__nv_bfloat16*)FERs)[ch * 16 + r] = __float2bfloat16(v);
        }
        __syncthreads();

#pragma unroll
        for (int j = 0; j < 8; j++) {
            const int lch = h4 * 8 + j;          // local channel in chunk (0..31)
            const int ch  = cc * CCH + lch;      // block-local channel, for Cs
            __nv_bfloat162 cv = *(__nv_bfloat162*)(Cs + ch * CPAD + t2);
            float c0 = __bfloat162float(cv.x);
            float c1 = __bfloat162float(cv.y);

            float w[14];
#pragma unroll
            for (int p = 0; p < 7; p++) {
                __nv_bfloat162 v = FEs[lch * (FEW / 2) + t2 / 2 + p];
                w[2 * p]     = __bfloat162float(v.x);
                w[2 * p + 1] = __bfloat162float(v.y);
            }
#pragma unroll
            for (int k = 0; k < KS; k++) {
                accB[k][0] += w[k] * c0;
                accB[k][1] += w[k + 1] * c1;
            }
#pragma unroll
            for (int p = 0; p < 5; p++) {
                __nv_bfloat162 v = FERs[lch * 8 + p];
                float f0 = __bfloat162float(v.x);
                float f1 = __bfloat162float(v.y);
                accR[2 * p][0]     += f0 * c0;
                accR[2 * p][1]     += f0 * c1;
                accR[2 * p + 1][0] += f1 * c0;
                accR[2 * p + 1][1] += f1 * c1;
            }
        }
        __syncthreads();
    }

    // ================= epilogue 3: reduce h4 quarters in SMEM, write QS=4 ==
    float2* RED = (float2*)smbuf;                  // overlays Cs/FEs (dead)
    const int by = blockIdx.y;
    const int c2i = t2 >> 1;                       // 0..63 (float2 col index)

    // Phase A: band  — RED[h4][KS][64]  (24.6 KB)
#pragma unroll
    for (int k = 0; k < KS; k++)
        RED[(h4 * KS + k) * 64 + c2i] = make_float2(accB[k][0], accB[k][1]);
    __syncthreads();
    for (int e = tid; e < KS * 64; e += 256) {
        int k = e >> 6, c2 = e & 63;
        float2 s0 = RED[(0 * KS + k) * 64 + c2];
        float2 s1 = RED[(1 * KS + k) * 64 + c2];
        float2 s2 = RED[(2 * KS + k) * 64 + c2];
        float2 s3 = RED[(3 * KS + k) * 64 + c2];
        float2 s = make_float2((s0.x + s1.x) + (s2.x + s3.x),
                               (s0.y + s1.y) + (s2.y + s3.y));
        *(float2*)&g_band_p[(((size_t)by * BB + b) * KS + k) * TT + t0 + c2 * 2] = s;
    }
    __syncthreads();

    // Phase B: rows  — RED[h4][NN][64]  (20.5 KB)
#pragma unroll
    for (int r = 0; r < NN; r++)
        RED[(h4 * NN + r) * 64 + c2i] = make_float2(accR[r][0], accR[r][1]);
    __syncthreads();
    for (int e = tid; e < NN * 64; e += 256) {
        int r = e >> 6, c2 = e & 63;
        float2 s0 = RED[(0 * NN + r) * 64 + c2];
        float2 s1 = RED[(1 * NN + r) * 64 + c2];
        float2 s2 = RED[(2 * NN + r) * 64 + c2];
        float2 s3 = RED[(3 * NN + r) * 64 + c2];
        float2 s = make_float2((s0.x + s1.x) + (s2.x + s3.x),
                               (s0.y + s1.y) + (s2.y + s3.y));
        *(float2*)&g_rows_p[(((size_t)by * BB + b) * NN + r) * TT + t0 + c2 * 2] = s;
    }
}

// ---------------------------------------------------------------------------
// Kernel C: combine partials (QS=4) + positives loss + interleaved ls table
// ---------------------------------------------------------------------------
__global__ __launch_bounds__(256) void combine_k() {
    const int NB = BB * KS * TT;
    const int NR = BB * NN * TT;
    int i = blockIdx.x * blockDim.x + threadIdx.x;
    double local = 0.0;
    if (i < NB) {
        float v = 0.f;
#pragma unroll
        for (int q = 0; q < QS; q++) v += g_band_p[(size_t)q * NB + i];
        int s = i % TT;
        int k = (i / TT) % KS;
        if (s + k < TT) local = (double)logsigf(v);
    } else if (i < NB + NR) {
        int j = i - NB;
        float v = 0.f;
#pragma unroll
        for (int q = 0; q < QS; q++) v += g_rows_p[(size_t)q * NR + j];
        int bq = j / (NN * TT);
        int r  = (j / TT) % NN;
        int s  = j % TT;
        float* dst = (float*)&g_ls2[(size_t)r * TT + s];
        dst[bq] = logsigf(-v);
    }
#pragma unroll
    for (int off = 16; off; off >>= 1)
        local += __shfl_down_sync(0xffffffffu, local, off);
    __shared__ double warp_sums[8];
    int lane = threadIdx.x & 31, wid = threadIdx.x >> 5;
    if (lane == 0) warp_sums[wid] = local;
    __syncthreads();
    if (wid == 0) {
        local = (lane < 8) ? warp_sums[lane] : 0.0;
#pragma unroll
        for (int off = 4; off; off >>= 1)
            local += __shfl_down_sync(0xffffffffu, local, off);
        if (lane == 0 && local != 0.0) atomicAdd(&g_total, local);
    }
}

// ---------------------------------------------------------------------------
// Kernel D: negatives — float2 gathers (Round-10 measured best) + final write
// ---------------------------------------------------------------------------
#define LGRID 960

__global__ __launch_bounds__(256) void loss_k(const int* __restrict__ neg_idx,
                                              float* __restrict__ out) {
    const int gid    = blockIdx.x * 256 + threadIdx.x;
    const int stride = LGRID * 256;            // 245760
    const int i0 = gid;
    const int i1 = gid + stride;
    const int r0 = i0 % NN, s0 = (i0 / NN) % TT, k0 = i0 / (NN * TT);
    const int r1 = i1 % NN, s1 = (i1 / NN) % TT, k1 = i1 / (NN * TT);
    int idx0 = __ldg(&neg_idx[(k0 * TT + s0) * NN + r0]);
    int idx1 = __ldg(&neg_idx[(k1 * TT + s1) * NN + r1]);
    float2 v0 = g_ls2[(size_t)r0 * TT + idx0];
    float2 v1 = g_ls2[(size_t)r1 * TT + idx1];
    float fsum = (v0.x + v0.y) + (v1.x + v1.y);
    double local = (double)NN * (double)fsum;

#pragma unroll
    for (int off = 16; off; off >>= 1)
        local += __shfl_down_sync(0xffffffffu, local, off);
    __shared__ double warp_sums[8];
    int lane = threadIdx.x & 31, wid = threadIdx.x >> 5;
    if (lane == 0) warp_sums[wid] = local;
    __syncthreads();
    if (wid == 0 && lane == 0) {
        local = 0.0;
#pragma unroll
        for (int w = 0; w < 8; w++) local += warp_sums[w];
        atomicAdd(&g_total, local);
        __threadfence();
        int done = atomicAdd(&g_done, 1);
        if (done == LGRID - 1) {
            __threadfence();
            double tot = atomicAdd(&g_total, 0.0);
            out[0] = (float)tot;
        }
    }
}

// ---------------------------------------------------------------------------
// Launch
// ---------------------------------------------------------------------------
extern "C" void kernel_launch(void* const* d_in, const int* in_sizes, int n_in,
                              void* d_out, int out_size) {
    const float* fe   = (const float*)d_in[0];  // feat_enc     [B,C,T]
    const float* fc   = (const float*)d_in[1];  // feat_context [B,C,T]
    const float* W    = (const float*)d_in[2];  // [C,C]
    const float* bias = (const float*)d_in[3];  // [C]
    const int*   neg  = (const int*)d_in[4];    // [K_STEPS,T,NUM_NEG]

    convw_k<<<(CH * CH / 2 + 255) / 256, 256>>>(W);

    fused_k<<<dim3(TT / BN, CH / BM, BB), 256>>>(fc, fe, bias);

    const int NTOT = BB * (KS + NN) * TT;
    combine_k<<<(NTOT + 255) / 256, 256>>>();

    loss_k<<<LGRID, 256>>>(neg, (float*)d_out);
}